// round 1
// baseline (speedup 1.0000x reference)
#include <cuda_runtime.h>
#include <math.h>

#define N_NODES 50000
#define N_EDGES 800000
#define DIM 64

// Scratch (device globals: allocation-free, allowed)
__device__ float g_out_deg[N_NODES];
__device__ float g_in_deg[N_NODES];
__device__ float g_agg[(size_t)N_NODES * DIM];

// ---------------------------------------------------------------------------
// 1) Zero scratch
// ---------------------------------------------------------------------------
__global__ void zero_kernel() {
    const int stride = gridDim.x * blockDim.x;
    int i = blockIdx.x * blockDim.x + threadIdx.x;
    const int total = N_NODES * DIM;
    for (int j = i; j < total; j += stride) g_agg[j] = 0.0f;
    for (int j = i; j < N_NODES; j += stride) {
        g_out_deg[j] = 0.0f;
        g_in_deg[j]  = 0.0f;
    }
}

// ---------------------------------------------------------------------------
// 2) Degrees: out_deg[src]++, in_deg[dst]++
// ---------------------------------------------------------------------------
__global__ void degree_kernel(const int* __restrict__ src,
                              const int* __restrict__ dst) {
    int i = blockIdx.x * blockDim.x + threadIdx.x;
    if (i < N_EDGES) {
        atomicAdd(&g_out_deg[src[i]], 1.0f);
        atomicAdd(&g_in_deg[dst[i]], 1.0f);
    }
}

// ---------------------------------------------------------------------------
// 3) Scatter-aggregate: agg[dst] += x[src] * rsqrt(out_deg[src]*in_deg[dst])
//    16 threads per edge, each handles 4 contiguous floats (float4),
//    reduced into L2 via red.global.add.v4.f32 (one 16B reduction per thread).
// ---------------------------------------------------------------------------
__global__ void scatter_kernel(const float* __restrict__ x,
                               const int* __restrict__ src,
                               const int* __restrict__ dst) {
    int t = blockIdx.x * blockDim.x + threadIdx.x;
    int e = t >> 4;
    if (e >= N_EDGES) return;
    int c = (t & 15) * 4;

    int s = __ldg(src + e);
    int d = __ldg(dst + e);

    float prod = __ldg(&g_out_deg[s]) * __ldg(&g_in_deg[d]);
    float norm = (prod > 0.0f) ? rsqrtf(prod) : 1.0f;

    float4 v = *reinterpret_cast<const float4*>(x + (size_t)s * DIM + c);
    v.x *= norm; v.y *= norm; v.z *= norm; v.w *= norm;

    float* p = g_agg + (size_t)d * DIM + c;
    asm volatile("red.global.add.v4.f32 [%0], {%1, %2, %3, %4};"
                 :: "l"(p), "f"(v.x), "f"(v.y), "f"(v.z), "f"(v.w)
                 : "memory");
}

// ---------------------------------------------------------------------------
// 4) FFN: out = gelu(agg @ w1 + b1) @ w2 + b2     (exact GELU, erf)
//    Warp-per-node: row in registers (2 floats/lane), weights in smem,
//    shfl-broadcast of the activation along K.
// ---------------------------------------------------------------------------
__global__ void __launch_bounds__(256) ffn_kernel(const float* __restrict__ w1,
                                                  const float* __restrict__ b1,
                                                  const float* __restrict__ w2,
                                                  const float* __restrict__ b2,
                                                  float* __restrict__ out) {
    __shared__ float s_w1[DIM * DIM];
    __shared__ float s_w2[DIM * DIM];
    __shared__ float s_b1[DIM];
    __shared__ float s_b2[DIM];

    for (int i = threadIdx.x; i < DIM * DIM; i += blockDim.x) {
        s_w1[i] = w1[i];
        s_w2[i] = w2[i];
    }
    if (threadIdx.x < DIM) {
        s_b1[threadIdx.x] = b1[threadIdx.x];
        s_b2[threadIdx.x] = b2[threadIdx.x];
    }
    __syncthreads();

    const int lane   = threadIdx.x & 31;
    const int warp   = (blockIdx.x * blockDim.x + threadIdx.x) >> 5;
    const int nwarps = (gridDim.x * blockDim.x) >> 5;
    const float inv_sqrt2 = 0.70710678118654752f;

    for (int n = warp; n < N_NODES; n += nwarps) {
        const float* row = g_agg + (size_t)n * DIM;
        float a0 = row[lane];
        float a1 = row[lane + 32];

        // h = agg @ w1 + b1
        float h0 = s_b1[lane];
        float h1 = s_b1[lane + 32];
        #pragma unroll
        for (int dd = 0; dd < 32; dd++) {
            float ad = __shfl_sync(0xffffffffu, a0, dd);
            h0 = fmaf(ad, s_w1[dd * DIM + lane], h0);
            h1 = fmaf(ad, s_w1[dd * DIM + lane + 32], h1);
        }
        #pragma unroll
        for (int dd = 0; dd < 32; dd++) {
            float ad = __shfl_sync(0xffffffffu, a1, dd);
            h0 = fmaf(ad, s_w1[(dd + 32) * DIM + lane], h0);
            h1 = fmaf(ad, s_w1[(dd + 32) * DIM + lane + 32], h1);
        }

        // exact GELU
        h0 = 0.5f * h0 * (1.0f + erff(h0 * inv_sqrt2));
        h1 = 0.5f * h1 * (1.0f + erff(h1 * inv_sqrt2));

        // out = h @ w2 + b2
        float o0 = s_b2[lane];
        float o1 = s_b2[lane + 32];
        #pragma unroll
        for (int dd = 0; dd < 32; dd++) {
            float hd = __shfl_sync(0xffffffffu, h0, dd);
            o0 = fmaf(hd, s_w2[dd * DIM + lane], o0);
            o1 = fmaf(hd, s_w2[dd * DIM + lane + 32], o1);
        }
        #pragma unroll
        for (int dd = 0; dd < 32; dd++) {
            float hd = __shfl_sync(0xffffffffu, h1, dd);
            o0 = fmaf(hd, s_w2[(dd + 32) * DIM + lane], o0);
            o1 = fmaf(hd, s_w2[(dd + 32) * DIM + lane + 32], o1);
        }

        out[(size_t)n * DIM + lane]      = o0;
        out[(size_t)n * DIM + lane + 32] = o1;
    }
}

// ---------------------------------------------------------------------------
// Launcher (graph-capturable: kernels only, default stream)
// Inputs per metadata order: x, edge_src, edge_dst, w1, b1, w2, b2
// ---------------------------------------------------------------------------
extern "C" void kernel_launch(void* const* d_in, const int* in_sizes, int n_in,
                              void* d_out, int out_size) {
    const float* x   = (const float*)d_in[0];
    const int*   src = (const int*)d_in[1];
    const int*   dst = (const int*)d_in[2];
    const float* w1  = (const float*)d_in[3];
    const float* b1  = (const float*)d_in[4];
    const float* w2  = (const float*)d_in[5];
    const float* b2  = (const float*)d_in[6];
    float* out = (float*)d_out;

    zero_kernel<<<2048, 256>>>();
    degree_kernel<<<(N_EDGES + 255) / 256, 256>>>(src, dst);
    {
        long long total_threads = (long long)N_EDGES * 16;
        int blocks = (int)((total_threads + 255) / 256);
        scatter_kernel<<<blocks, 256>>>(x, src, dst);
    }
    ffn_kernel<<<592, 256>>>(w1, b1, w2, b2, out);
}

// round 2
// speedup vs baseline: 1.4886x; 1.4886x over previous
#include <cuda_runtime.h>
#include <math.h>

#define N_NODES 50000
#define N_EDGES 800000
#define DIM 64
#define TILE_M 64   // nodes per block in FFN

// Scratch (device globals: allocation-free, allowed)
__device__ float g_out_deg[N_NODES];
__device__ float g_in_deg[N_NODES];
__device__ float g_agg[(size_t)N_NODES * DIM];

// ---------------------------------------------------------------------------
// 1) Zero scratch
// ---------------------------------------------------------------------------
__global__ void zero_kernel() {
    const int stride = gridDim.x * blockDim.x;
    int i = blockIdx.x * blockDim.x + threadIdx.x;
    const int total = N_NODES * DIM;
    for (int j = i; j < total; j += stride) g_agg[j] = 0.0f;
    for (int j = i; j < N_NODES; j += stride) {
        g_out_deg[j] = 0.0f;
        g_in_deg[j]  = 0.0f;
    }
}

// ---------------------------------------------------------------------------
// 2) Degrees: out_deg[src]++, in_deg[dst]++
// ---------------------------------------------------------------------------
__global__ void degree_kernel(const int* __restrict__ src,
                              const int* __restrict__ dst) {
    int i = blockIdx.x * blockDim.x + threadIdx.x;
    if (i < N_EDGES) {
        atomicAdd(&g_out_deg[src[i]], 1.0f);
        atomicAdd(&g_in_deg[dst[i]], 1.0f);
    }
}

// ---------------------------------------------------------------------------
// 3) Scatter-aggregate: agg[dst] += x[src] * rsqrt(out_deg[src]*in_deg[dst])
//    16 threads per edge, float4 each, red.global.add.v4.f32 into L2.
// ---------------------------------------------------------------------------
__global__ void scatter_kernel(const float* __restrict__ x,
                               const int* __restrict__ src,
                               const int* __restrict__ dst) {
    int t = blockIdx.x * blockDim.x + threadIdx.x;
    int e = t >> 4;
    if (e >= N_EDGES) return;
    int c = (t & 15) * 4;

    int s = __ldg(src + e);
    int d = __ldg(dst + e);

    float prod = __ldg(&g_out_deg[s]) * __ldg(&g_in_deg[d]);
    float norm = (prod > 0.0f) ? rsqrtf(prod) : 1.0f;

    float4 v = *reinterpret_cast<const float4*>(x + (size_t)s * DIM + c);
    v.x *= norm; v.y *= norm; v.z *= norm; v.w *= norm;

    float* p = g_agg + (size_t)d * DIM + c;
    asm volatile("red.global.add.v4.f32 [%0], {%1, %2, %3, %4};"
                 :: "l"(p), "f"(v.x), "f"(v.y), "f"(v.z), "f"(v.w)
                 : "memory");
}

// ---------------------------------------------------------------------------
// 4) FFN: out = gelu(agg @ w1 + b1) @ w2 + b2
//    Register-tiled GEMM. Block = 64 nodes x 64 cols, 128 threads,
//    thread tile = 4 nodes x 8 cols. agg tile transposed k-major in smem.
//    Conflict-free LDS: a-loads strided (node = tn + 16*i), w-loads broadcast.
// ---------------------------------------------------------------------------
__global__ void __launch_bounds__(128) ffn_kernel(const float* __restrict__ w1,
                                                  const float* __restrict__ b1,
                                                  const float* __restrict__ w2,
                                                  const float* __restrict__ b2,
                                                  float* __restrict__ out) {
    __shared__ float sT[DIM * TILE_M];    // [k][node]  16KB (reused for h)
    __shared__ float s_w1[DIM * DIM];     // [k][col]   16KB
    __shared__ float s_w2[DIM * DIM];     // [k][col]   16KB

    const int tid  = threadIdx.x;
    const int base = blockIdx.x * TILE_M;

    // Load weights
    #pragma unroll
    for (int i = tid; i < DIM * DIM; i += 128) {
        s_w1[i] = w1[i];
        s_w2[i] = w2[i];
    }

    // Fill sT = transpose of agg tile. r = node-in-tile (0..63), k40 = 0/1.
    {
        const int r   = tid & 63;
        const int k40 = tid >> 6;
        const int node = base + r;
        #pragma unroll
        for (int it = 0; it < 8; it++) {
            int k4 = k40 + 2 * it;
            float4 v = make_float4(0.f, 0.f, 0.f, 0.f);
            if (node < N_NODES)
                v = *reinterpret_cast<const float4*>(g_agg + (size_t)node * DIM + k4 * 4);
            sT[(k4 * 4 + 0) * TILE_M + r] = v.x;
            sT[(k4 * 4 + 1) * TILE_M + r] = v.y;
            sT[(k4 * 4 + 2) * TILE_M + r] = v.z;
            sT[(k4 * 4 + 3) * TILE_M + r] = v.w;
        }
    }
    __syncthreads();

    const int tn = tid & 15;   // node group: nodes tn + 16*i
    const int tc = tid >> 4;   // col group:  cols  tc*8 + j

    // ---- GEMM1: h = agg @ w1 + b1 ----
    float acc[4][8];
    #pragma unroll
    for (int j = 0; j < 8; j++) {
        float bj = __ldg(b1 + tc * 8 + j);
        #pragma unroll
        for (int i = 0; i < 4; i++) acc[i][j] = bj;
    }

    #pragma unroll 8
    for (int k = 0; k < DIM; k++) {
        float a[4], w[8];
        #pragma unroll
        for (int i = 0; i < 4; i++) a[i] = sT[k * TILE_M + tn + 16 * i];
        #pragma unroll
        for (int j = 0; j < 8; j++) w[j] = s_w1[k * DIM + tc * 8 + j];
        #pragma unroll
        for (int i = 0; i < 4; i++)
            #pragma unroll
            for (int j = 0; j < 8; j++)
                acc[i][j] = fmaf(a[i], w[j], acc[i][j]);
    }

    // exact GELU
    const float inv_sqrt2 = 0.70710678118654752f;
    #pragma unroll
    for (int i = 0; i < 4; i++)
        #pragma unroll
        for (int j = 0; j < 8; j++) {
            float h = acc[i][j];
            acc[i][j] = 0.5f * h * (1.0f + erff(h * inv_sqrt2));
        }

    __syncthreads();  // all GEMM1 reads of sT done before overwrite

    // store h k-major into sT: sT[col][node]
    #pragma unroll
    for (int i = 0; i < 4; i++)
        #pragma unroll
        for (int j = 0; j < 8; j++)
            sT[(tc * 8 + j) * TILE_M + tn + 16 * i] = acc[i][j];

    __syncthreads();

    // ---- GEMM2: out = h @ w2 + b2 ----
    float acc2[4][8];
    #pragma unroll
    for (int j = 0; j < 8; j++) {
        float bj = __ldg(b2 + tc * 8 + j);
        #pragma unroll
        for (int i = 0; i < 4; i++) acc2[i][j] = bj;
    }

    #pragma unroll 8
    for (int k = 0; k < DIM; k++) {
        float a[4], w[8];
        #pragma unroll
        for (int i = 0; i < 4; i++) a[i] = sT[k * TILE_M + tn + 16 * i];
        #pragma unroll
        for (int j = 0; j < 8; j++) w[j] = s_w2[k * DIM + tc * 8 + j];
        #pragma unroll
        for (int i = 0; i < 4; i++)
            #pragma unroll
            for (int j = 0; j < 8; j++)
                acc2[i][j] = fmaf(a[i], w[j], acc2[i][j]);
    }

    // store output (2x float4 per node)
    #pragma unroll
    for (int i = 0; i < 4; i++) {
        int node = base + tn + 16 * i;
        if (node < N_NODES) {
            float4 v0 = make_float4(acc2[i][0], acc2[i][1], acc2[i][2], acc2[i][3]);
            float4 v1 = make_float4(acc2[i][4], acc2[i][5], acc2[i][6], acc2[i][7]);
            float* p = out + (size_t)node * DIM + tc * 8;
            *reinterpret_cast<float4*>(p)     = v0;
            *reinterpret_cast<float4*>(p + 4) = v1;
        }
    }
}

// ---------------------------------------------------------------------------
// Launcher. Inputs: x, edge_src, edge_dst, w1, b1, w2, b2
// ---------------------------------------------------------------------------
extern "C" void kernel_launch(void* const* d_in, const int* in_sizes, int n_in,
                              void* d_out, int out_size) {
    const float* x   = (const float*)d_in[0];
    const int*   src = (const int*)d_in[1];
    const int*   dst = (const int*)d_in[2];
    const float* w1  = (const float*)d_in[3];
    const float* b1  = (const float*)d_in[4];
    const float* w2  = (const float*)d_in[5];
    const float* b2  = (const float*)d_in[6];
    float* out = (float*)d_out;

    zero_kernel<<<2048, 256>>>();
    degree_kernel<<<(N_EDGES + 255) / 256, 256>>>(src, dst);
    {
        long long total_threads = (long long)N_EDGES * 16;
        int blocks = (int)((total_threads + 255) / 256);
        scatter_kernel<<<blocks, 256>>>(x, src, dst);
    }
    {
        int blocks = (N_NODES + TILE_M - 1) / TILE_M;   // 782
        ffn_kernel<<<blocks, 128>>>(w1, b1, w2, b2, out);
    }
}

// round 3
// speedup vs baseline: 1.5493x; 1.0408x over previous
#include <cuda_runtime.h>
#include <math.h>

#define N_NODES 50000
#define N_EDGES 800000
#define DIM 64
#define TILE_M 64
#define NP 196   // ceil(N_NODES / 256)

// Scratch (device globals)
__device__ int   g_out_cnt[N_NODES];
__device__ int   g_in_cnt[N_NODES];
__device__ int   g_row_start[N_NODES];
__device__ int   g_cursor[N_NODES];
__device__ int   g_perm[N_EDGES];
__device__ int   g_partial[256];
__device__ float g_agg[(size_t)N_NODES * DIM];

// ---------------------------------------------------------------------------
// 0) Zero counters
// ---------------------------------------------------------------------------
__global__ void zero_kernel() {
    int i = blockIdx.x * blockDim.x + threadIdx.x;
    if (i < N_NODES) {
        g_out_cnt[i] = 0;
        g_in_cnt[i]  = 0;
    }
}

// ---------------------------------------------------------------------------
// 1) Histogram: out_cnt[src]++, in_cnt[dst]++  (RED, no return)
// ---------------------------------------------------------------------------
__global__ void hist_kernel(const int* __restrict__ src,
                            const int* __restrict__ dst) {
    int i = blockIdx.x * blockDim.x + threadIdx.x;
    if (i < N_EDGES) {
        atomicAdd(&g_out_cnt[src[i]], 1);
        atomicAdd(&g_in_cnt[dst[i]], 1);
    }
}

// ---------------------------------------------------------------------------
// 2) Exclusive scan of in_cnt -> row_start (3 tiny kernels)
// ---------------------------------------------------------------------------
__global__ void scanA_kernel() {   // per-block sums
    __shared__ int sm[256];
    int t = threadIdx.x;
    int i = blockIdx.x * 256 + t;
    int v = (i < N_NODES) ? g_in_cnt[i] : 0;
    sm[t] = v;
    __syncthreads();
    #pragma unroll
    for (int off = 1; off < 256; off <<= 1) {
        int xv = (t >= off) ? sm[t - off] : 0;
        __syncthreads();
        sm[t] += xv;
        __syncthreads();
    }
    if (t == 255) g_partial[blockIdx.x] = sm[255];
}

__global__ void scanB_kernel() {   // scan the 196 partials (1 block)
    __shared__ int sm[256];
    int t = threadIdx.x;
    int v = (t < NP) ? g_partial[t] : 0;
    sm[t] = v;
    __syncthreads();
    #pragma unroll
    for (int off = 1; off < 256; off <<= 1) {
        int xv = (t >= off) ? sm[t - off] : 0;
        __syncthreads();
        sm[t] += xv;
        __syncthreads();
    }
    if (t < NP) g_partial[t] = sm[t] - v;   // exclusive
}

__global__ void scanC_kernel() {   // block-local exclusive + base -> row_start, cursor
    __shared__ int sm[256];
    int t = threadIdx.x;
    int i = blockIdx.x * 256 + t;
    int v = (i < N_NODES) ? g_in_cnt[i] : 0;
    sm[t] = v;
    __syncthreads();
    #pragma unroll
    for (int off = 1; off < 256; off <<= 1) {
        int xv = (t >= off) ? sm[t - off] : 0;
        __syncthreads();
        sm[t] += xv;
        __syncthreads();
    }
    if (i < N_NODES) {
        int start = g_partial[blockIdx.x] + sm[t] - v;
        g_row_start[i] = start;
        g_cursor[i]    = start;
    }
}

// ---------------------------------------------------------------------------
// 3) Fill: perm[cursor[dst]++] = src
// ---------------------------------------------------------------------------
__global__ void fill_kernel(const int* __restrict__ src,
                            const int* __restrict__ dst) {
    int i = blockIdx.x * blockDim.x + threadIdx.x;
    if (i < N_EDGES) {
        int pos = atomicAdd(&g_cursor[dst[i]], 1);
        g_perm[pos] = src[i];
    }
}

// ---------------------------------------------------------------------------
// 4) Gather-aggregate: warp per dst node, register accumulation, single write.
// ---------------------------------------------------------------------------
__global__ void __launch_bounds__(256) gather_kernel(const float* __restrict__ x) {
    int warp = (blockIdx.x * blockDim.x + threadIdx.x) >> 5;
    if (warp >= N_NODES) return;
    const int lane = threadIdx.x & 31;

    const int deg   = g_in_cnt[warp];
    const int start = g_row_start[warp];
    const float indeg = (float)deg;

    float acc0 = 0.0f, acc1 = 0.0f;
    int j = start;
    const int end = start + deg;

    for (; j + 2 <= end; j += 2) {
        int s0 = __ldg(g_perm + j);
        int s1 = __ldg(g_perm + j + 1);
        float n0 = rsqrtf((float)__ldg(g_out_cnt + s0) * indeg);
        float n1 = rsqrtf((float)__ldg(g_out_cnt + s1) * indeg);
        float a00 = __ldg(x + (size_t)s0 * DIM + lane);
        float a01 = __ldg(x + (size_t)s0 * DIM + lane + 32);
        float a10 = __ldg(x + (size_t)s1 * DIM + lane);
        float a11 = __ldg(x + (size_t)s1 * DIM + lane + 32);
        acc0 = fmaf(a00, n0, acc0);
        acc1 = fmaf(a01, n0, acc1);
        acc0 = fmaf(a10, n1, acc0);
        acc1 = fmaf(a11, n1, acc1);
    }
    if (j < end) {
        int s0 = __ldg(g_perm + j);
        float n0 = rsqrtf((float)__ldg(g_out_cnt + s0) * indeg);
        acc0 = fmaf(__ldg(x + (size_t)s0 * DIM + lane),      n0, acc0);
        acc1 = fmaf(__ldg(x + (size_t)s0 * DIM + lane + 32), n0, acc1);
    }

    g_agg[(size_t)warp * DIM + lane]      = acc0;
    g_agg[(size_t)warp * DIM + lane + 32] = acc1;
}

// ---------------------------------------------------------------------------
// 5) FFN: out = gelu(agg @ w1 + b1) @ w2 + b2
//    64x64 block tile, 128 threads, 4x8 thread tile, vectorized w-loads.
// ---------------------------------------------------------------------------
__global__ void __launch_bounds__(128) ffn_kernel(const float* __restrict__ w1,
                                                  const float* __restrict__ b1,
                                                  const float* __restrict__ w2,
                                                  const float* __restrict__ b2,
                                                  float* __restrict__ out) {
    __shared__ float sT[DIM * TILE_M];    // [k][node], reused for h
    __shared__ float s_w1[DIM * DIM];
    __shared__ float s_w2[DIM * DIM];

    const int tid  = threadIdx.x;
    const int base = blockIdx.x * TILE_M;

    #pragma unroll
    for (int i = tid; i < DIM * DIM; i += 128) {
        s_w1[i] = w1[i];
        s_w2[i] = w2[i];
    }

    // sT = transpose of agg tile
    {
        const int r   = tid & 63;
        const int k40 = tid >> 6;
        const int node = base + r;
        #pragma unroll
        for (int it = 0; it < 8; it++) {
            int k4 = k40 + 2 * it;
            float4 v = make_float4(0.f, 0.f, 0.f, 0.f);
            if (node < N_NODES)
                v = *reinterpret_cast<const float4*>(g_agg + (size_t)node * DIM + k4 * 4);
            sT[(k4 * 4 + 0) * TILE_M + r] = v.x;
            sT[(k4 * 4 + 1) * TILE_M + r] = v.y;
            sT[(k4 * 4 + 2) * TILE_M + r] = v.z;
            sT[(k4 * 4 + 3) * TILE_M + r] = v.w;
        }
    }
    __syncthreads();

    const int tn = tid & 15;
    const int tc = tid >> 4;

    // ---- GEMM1 ----
    float acc[4][8];
    {
        float4 bj0 = __ldg((const float4*)(b1 + tc * 8));
        float4 bj1 = __ldg((const float4*)(b1 + tc * 8 + 4));
        #pragma unroll
        for (int i = 0; i < 4; i++) {
            acc[i][0] = bj0.x; acc[i][1] = bj0.y; acc[i][2] = bj0.z; acc[i][3] = bj0.w;
            acc[i][4] = bj1.x; acc[i][5] = bj1.y; acc[i][6] = bj1.z; acc[i][7] = bj1.w;
        }
    }

    #pragma unroll 8
    for (int k = 0; k < DIM; k++) {
        float a[4];
        #pragma unroll
        for (int i = 0; i < 4; i++) a[i] = sT[k * TILE_M + tn + 16 * i];
        float4 wv0 = *reinterpret_cast<const float4*>(&s_w1[k * DIM + tc * 8]);
        float4 wv1 = *reinterpret_cast<const float4*>(&s_w1[k * DIM + tc * 8 + 4]);
        float w[8] = {wv0.x, wv0.y, wv0.z, wv0.w, wv1.x, wv1.y, wv1.z, wv1.w};
        #pragma unroll
        for (int i = 0; i < 4; i++)
            #pragma unroll
            for (int j = 0; j < 8; j++)
                acc[i][j] = fmaf(a[i], w[j], acc[i][j]);
    }

    // exact GELU
    const float inv_sqrt2 = 0.70710678118654752f;
    #pragma unroll
    for (int i = 0; i < 4; i++)
        #pragma unroll
        for (int j = 0; j < 8; j++) {
            float h = acc[i][j];
            acc[i][j] = 0.5f * h * (1.0f + erff(h * inv_sqrt2));
        }

    __syncthreads();

    #pragma unroll
    for (int i = 0; i < 4; i++)
        #pragma unroll
        for (int j = 0; j < 8; j++)
            sT[(tc * 8 + j) * TILE_M + tn + 16 * i] = acc[i][j];

    __syncthreads();

    // ---- GEMM2 ----
    float acc2[4][8];
    {
        float4 bj0 = __ldg((const float4*)(b2 + tc * 8));
        float4 bj1 = __ldg((const float4*)(b2 + tc * 8 + 4));
        #pragma unroll
        for (int i = 0; i < 4; i++) {
            acc2[i][0] = bj0.x; acc2[i][1] = bj0.y; acc2[i][2] = bj0.z; acc2[i][3] = bj0.w;
            acc2[i][4] = bj1.x; acc2[i][5] = bj1.y; acc2[i][6] = bj1.z; acc2[i][7] = bj1.w;
        }
    }

    #pragma unroll 8
    for (int k = 0; k < DIM; k++) {
        float a[4];
        #pragma unroll
        for (int i = 0; i < 4; i++) a[i] = sT[k * TILE_M + tn + 16 * i];
        float4 wv0 = *reinterpret_cast<const float4*>(&s_w2[k * DIM + tc * 8]);
        float4 wv1 = *reinterpret_cast<const float4*>(&s_w2[k * DIM + tc * 8 + 4]);
        float w[8] = {wv0.x, wv0.y, wv0.z, wv0.w, wv1.x, wv1.y, wv1.z, wv1.w};
        #pragma unroll
        for (int i = 0; i < 4; i++)
            #pragma unroll
            for (int j = 0; j < 8; j++)
                acc2[i][j] = fmaf(a[i], w[j], acc2[i][j]);
    }

    #pragma unroll
    for (int i = 0; i < 4; i++) {
        int node = base + tn + 16 * i;
        if (node < N_NODES) {
            float4 v0 = make_float4(acc2[i][0], acc2[i][1], acc2[i][2], acc2[i][3]);
            float4 v1 = make_float4(acc2[i][4], acc2[i][5], acc2[i][6], acc2[i][7]);
            float* p = out + (size_t)node * DIM + tc * 8;
            *reinterpret_cast<float4*>(p)     = v0;
            *reinterpret_cast<float4*>(p + 4) = v1;
        }
    }
}

// ---------------------------------------------------------------------------
// Launcher. Inputs: x, edge_src, edge_dst, w1, b1, w2, b2
// ---------------------------------------------------------------------------
extern "C" void kernel_launch(void* const* d_in, const int* in_sizes, int n_in,
                              void* d_out, int out_size) {
    const float* x   = (const float*)d_in[0];
    const int*   src = (const int*)d_in[1];
    const int*   dst = (const int*)d_in[2];
    const float* w1  = (const float*)d_in[3];
    const float* b1  = (const float*)d_in[4];
    const float* w2  = (const float*)d_in[5];
    const float* b2  = (const float*)d_in[6];
    float* out = (float*)d_out;

    zero_kernel<<<NP, 256>>>();
    hist_kernel<<<(N_EDGES + 255) / 256, 256>>>(src, dst);
    scanA_kernel<<<NP, 256>>>();
    scanB_kernel<<<1, 256>>>();
    scanC_kernel<<<NP, 256>>>();
    fill_kernel<<<(N_EDGES + 255) / 256, 256>>>(src, dst);
    gather_kernel<<<(N_NODES * 32 + 255) / 256, 256>>>(x);
    ffn_kernel<<<(N_NODES + TILE_M - 1) / TILE_M, 128>>>(w1, b1, w2, b2, out);
}